// round 10
// baseline (speedup 1.0000x reference)
#include <cuda_runtime.h>

// Problem constants
#define BB 16
#define CC 512
#define TT 1024
#define NH 8
#define HD 64

// Scratch (static device globals — allocation-free per harness rules)
__device__ float g_q[(size_t)BB * NH * TT * HD];
__device__ float g_k[(size_t)BB * NH * TT * HD];
__device__ float g_v[(size_t)BB * NH * TT * HD];
__device__ float g_att[(size_t)BB * NH * TT * HD];
__device__ float g_orot[(size_t)BB * CC * TT];

// ---------------------------------------------------------------------------
// tf32 helpers
// ---------------------------------------------------------------------------
__device__ __forceinline__ unsigned f2tf(float x) {
  unsigned r;
  asm("cvt.rna.tf32.f32 %0, %1;" : "=r"(r) : "f"(x));
  return r;
}
__device__ __forceinline__ float f2tf_f(float x) {
  return __uint_as_float(f2tf(x));
}
// D(16x8) += A(16x8) * B(8x8), tf32 in, fp32 accum.
__device__ __forceinline__ void mma8(float* c, unsigned a0, unsigned a1,
                                     unsigned a2, unsigned a3, unsigned b0,
                                     unsigned b1) {
  asm volatile(
      "mma.sync.aligned.m16n8k8.row.col.f32.tf32.tf32.f32 "
      "{%0,%1,%2,%3},{%4,%5,%6,%7},{%8,%9},{%0,%1,%2,%3};\n"
      : "+f"(c[0]), "+f"(c[1]), "+f"(c[2]), "+f"(c[3])
      : "r"(a0), "r"(a1), "r"(a2), "r"(a3), "r"(b0), "r"(b1));
}

// ---------------------------------------------------------------------------
// tf32 GEMM: out[b][m][n] = sum_k A[m][k] * Xsrc[b][k][n] + bias[m]
// b_from_orot: B matrix source resolved IN DEVICE CODE (g_orot) — passing a
// __device__ symbol from host code passes the host shadow address (the bug
// that produced out=bias in rounds 5-9).
// As[m][k] stride 20, Bs[k][n] stride 136. BM=128, BN=128, BK=16.
// 8 warps 2(m) x 4(n), warp tile 64x32, mma = m16n8k8.
// ---------------------------------------------------------------------------
__global__ __launch_bounds__(256) void mm_tf32_kernel(
    const float* __restrict__ A, const float* __restrict__ Bx,
    const float* __restrict__ bias, float* __restrict__ out, int qkv_mode,
    int b_from_orot) {
  __shared__ float As[128 * 20];
  __shared__ float Bs[16 * 136];
  const int b = blockIdx.z;
  const int bm = blockIdx.y * 128;
  const int bn = blockIdx.x * 128;
  const int tid = threadIdx.x;
  const int lane = tid & 31, warp = tid >> 5;
  const int wm = warp >> 2, wn = warp & 3;
  const int g = lane >> 2, tig = lane & 3;
  const float* bsrc = b_from_orot ? (const float*)g_orot : Bx;
  const float* xb = bsrc + (size_t)b * CC * TT;

  float c[4][4][4];
#pragma unroll
  for (int i = 0; i < 4; i++)
#pragma unroll
    for (int j = 0; j < 4; j++)
#pragma unroll
      for (int e = 0; e < 4; e++) c[i][j][e] = 0.f;

  const int am = tid >> 2, akq = tid & 3;         // A rows am, am+64
  const int br = tid >> 5, bc = (tid & 31) << 2;  // B rows br, br+8

  float4 a0r, a1r, b0r, b1r;
  a0r = *(const float4*)(A + (size_t)(bm + am) * CC + akq * 4);
  a1r = *(const float4*)(A + (size_t)(bm + am + 64) * CC + akq * 4);
  b0r = *(const float4*)(xb + (size_t)br * TT + bn + bc);
  b1r = *(const float4*)(xb + (size_t)(br + 8) * TT + bn + bc);

  for (int kb = 0; kb < 32; kb++) {
    *(float4*)&As[am * 20 + akq * 4] =
        make_float4(f2tf_f(a0r.x), f2tf_f(a0r.y), f2tf_f(a0r.z), f2tf_f(a0r.w));
    *(float4*)&As[(am + 64) * 20 + akq * 4] =
        make_float4(f2tf_f(a1r.x), f2tf_f(a1r.y), f2tf_f(a1r.z), f2tf_f(a1r.w));
    *(float4*)&Bs[br * 136 + bc] =
        make_float4(f2tf_f(b0r.x), f2tf_f(b0r.y), f2tf_f(b0r.z), f2tf_f(b0r.w));
    *(float4*)&Bs[(br + 8) * 136 + bc] =
        make_float4(f2tf_f(b1r.x), f2tf_f(b1r.y), f2tf_f(b1r.z), f2tf_f(b1r.w));
    __syncthreads();
    if (kb + 1 < 32) {
      const int k0 = (kb + 1) * 16;
      a0r = *(const float4*)(A + (size_t)(bm + am) * CC + k0 + akq * 4);
      a1r = *(const float4*)(A + (size_t)(bm + am + 64) * CC + k0 + akq * 4);
      b0r = *(const float4*)(xb + (size_t)(k0 + br) * TT + bn + bc);
      b1r = *(const float4*)(xb + (size_t)(k0 + br + 8) * TT + bn + bc);
    }
#pragma unroll
    for (int ks = 0; ks < 2; ks++) {
      unsigned a[4][4];
#pragma unroll
      for (int i = 0; i < 4; i++) {
        const int m0 = (wm * 64 + i * 16 + g) * 20 + ks * 8 + tig;
        a[i][0] = __float_as_uint(As[m0]);        // (m, k)
        a[i][1] = __float_as_uint(As[m0 + 160]);  // (m+8, k)
        a[i][2] = __float_as_uint(As[m0 + 4]);    // (m, k+4)
        a[i][3] = __float_as_uint(As[m0 + 164]);  // (m+8, k+4)
      }
      unsigned bb0[4], bb1[4];
#pragma unroll
      for (int j = 0; j < 4; j++) {
        const int nb = (ks * 8 + tig) * 136 + wn * 32 + j * 8 + g;
        bb0[j] = __float_as_uint(Bs[nb]);        // (k,   n)
        bb1[j] = __float_as_uint(Bs[nb + 544]);  // (k+4, n)
      }
#pragma unroll
      for (int i = 0; i < 4; i++)
#pragma unroll
        for (int j = 0; j < 4; j++)
          mma8(c[i][j], a[i][0], a[i][1], a[i][2], a[i][3], bb0[j], bb1[j]);
    }
    __syncthreads();
  }

  // Epilogue (C layout: rows g/g+8, cols 2tig/2tig+1 per 8-wide ntile)
  if (qkv_mode) {
#pragma unroll
    for (int i = 0; i < 4; i++) {
#pragma unroll
      for (int h = 0; h < 2; h++) {
        const int o = bm + wm * 64 + i * 16 + g + h * 8;
        const float bi = __ldg(bias + o);
        const int which = o >> 9;
        const int ch = o & 511;
        const int nh = ch & 7;
        const int d = ch >> 3;
        float* dst = (which == 0) ? g_q : (which == 1) ? g_k : g_v;
        const size_t base = (((size_t)b * NH + nh) * TT) * HD + d;
#pragma unroll
        for (int j = 0; j < 4; j++) {
#pragma unroll
          for (int cc = 0; cc < 2; cc++) {
            const int t = bn + wn * 32 + j * 8 + 2 * tig + cc;
            dst[base + (size_t)t * HD] = c[i][j][h * 2 + cc] + bi;
          }
        }
      }
    }
  } else {
#pragma unroll
    for (int i = 0; i < 4; i++) {
#pragma unroll
      for (int h = 0; h < 2; h++) {
        const int oc = bm + wm * 64 + i * 16 + g + h * 8;
        const float bi = __ldg(bias + oc);
        float* dst = out + ((size_t)b * CC + oc) * TT + bn + wn * 32 + 2 * tig;
#pragma unroll
        for (int j = 0; j < 4; j++) {
          *(float2*)(dst + j * 8) =
              make_float2(c[i][j][h * 2] + bi, c[i][j][h * 2 + 1] + bi);
        }
      }
    }
  }
}

// ---------------------------------------------------------------------------
// Kernel 2: in-place SO(2) rotation on q, k, v (PROVEN round 4, unchanged).
// ---------------------------------------------------------------------------
__global__ __launch_bounds__(128) void rotary_qkv_kernel(
    const float* __restrict__ mq, const float* __restrict__ mk,
    const float* __restrict__ mv) {
  const int which = blockIdx.y;
  float* buf = (which == 0) ? g_q : (which == 1) ? g_k : g_v;
  const float* mat = (which == 0) ? mq : (which == 1) ? mk : mv;
  const int row = blockIdx.x * blockDim.x + threadIdx.x;
  const int t = row & (TT - 1);
  float4* p = (float4*)(buf + (size_t)row * HD);
  const float4* m = (const float4*)(mat + (size_t)t * 128);
#pragma unroll
  for (int i = 0; i < 16; i++) {
    float4 v = p[i];
    float4 m0 = m[2 * i];
    float4 m1 = m[2 * i + 1];
    float4 o;
    o.x = m0.x * v.x + m0.y * v.y;
    o.y = m0.z * v.x + m0.w * v.y;
    o.z = m1.x * v.z + m1.y * v.w;
    o.w = m1.z * v.z + m1.w * v.w;
    p[i] = o;
  }
}

// ---------------------------------------------------------------------------
// Kernel 3: flash-style attention (PROVEN round 4 fp32 version, unchanged).
// ---------------------------------------------------------------------------
extern __shared__ float attn_sm[];

__global__ __launch_bounds__(256) void attn_kernel() {
  float* Qs = attn_sm;       // 64*64
  float* Ks = Qs + 64 * 64;  // 64*65 (transposed: [d][j])
  float* Vs = Ks + 64 * 65;  // 64*64
  float* Ps = Vs + 64 * 64;  // 64*68
  const int bh = blockIdx.y;
  const int qb = blockIdx.x * 64;
  const int tid = threadIdx.x;
  const int tx = tid & 15, ty = tid >> 4;
  const float* Qg = g_q + ((size_t)bh * TT + qb) * HD;
  const float* Kg = g_k + (size_t)bh * TT * HD;
  const float* Vg = g_v + (size_t)bh * TT * HD;
  const float scale = 0.125f;

  {
    const int r0 = tid >> 4;
    const int d0 = (tid & 15) << 2;
#pragma unroll
    for (int it = 0; it < 4; it++) {
      const int row = r0 + it * 16;
      float4 v = *(const float4*)(Qg + (size_t)row * HD + d0);
      v.x *= scale; v.y *= scale; v.z *= scale; v.w *= scale;
      *(float4*)(Qs + row * 64 + d0) = v;
    }
  }

  float m[4], l[4], o[4][4];
#pragma unroll
  for (int r = 0; r < 4; r++) {
    m[r] = -1e30f;
    l[r] = 0.f;
#pragma unroll
    for (int c = 0; c < 4; c++) o[r][c] = 0.f;
  }

  for (int kb = 0; kb < TT; kb += 64) {
    __syncthreads();
    {
      const int r0 = tid >> 4;
      const int d0 = (tid & 15) << 2;
#pragma unroll
      for (int it = 0; it < 4; it++) {
        const int row = r0 + it * 16;
        float4 kv = *(const float4*)(Kg + (size_t)(kb + row) * HD + d0);
        Ks[(d0 + 0) * 65 + row] = kv.x;
        Ks[(d0 + 1) * 65 + row] = kv.y;
        Ks[(d0 + 2) * 65 + row] = kv.z;
        Ks[(d0 + 3) * 65 + row] = kv.w;
        float4 vv = *(const float4*)(Vg + (size_t)(kb + row) * HD + d0);
        *(float4*)(Vs + row * 64 + d0) = vv;
      }
    }
    __syncthreads();

    float s[4][4];
#pragma unroll
    for (int r = 0; r < 4; r++)
#pragma unroll
      for (int c = 0; c < 4; c++) s[r][c] = 0.f;
#pragma unroll 16
    for (int d = 0; d < 64; d++) {
      float a0 = Qs[(ty * 4 + 0) * 64 + d];
      float a1 = Qs[(ty * 4 + 1) * 64 + d];
      float a2 = Qs[(ty * 4 + 2) * 64 + d];
      float a3 = Qs[(ty * 4 + 3) * 64 + d];
      float b0 = Ks[d * 65 + tx * 4 + 0];
      float b1 = Ks[d * 65 + tx * 4 + 1];
      float b2 = Ks[d * 65 + tx * 4 + 2];
      float b3 = Ks[d * 65 + tx * 4 + 3];
      s[0][0] += a0 * b0; s[0][1] += a0 * b1; s[0][2] += a0 * b2; s[0][3] += a0 * b3;
      s[1][0] += a1 * b0; s[1][1] += a1 * b1; s[1][2] += a1 * b2; s[1][3] += a1 * b3;
      s[2][0] += a2 * b0; s[2][1] += a2 * b1; s[2][2] += a2 * b2; s[2][3] += a2 * b3;
      s[3][0] += a3 * b0; s[3][1] += a3 * b1; s[3][2] += a3 * b2; s[3][3] += a3 * b3;
    }

#pragma unroll
    for (int r = 0; r < 4; r++) {
      float rmax = fmaxf(fmaxf(s[r][0], s[r][1]), fmaxf(s[r][2], s[r][3]));
      rmax = fmaxf(rmax, __shfl_xor_sync(0xffffffffu, rmax, 1));
      rmax = fmaxf(rmax, __shfl_xor_sync(0xffffffffu, rmax, 2));
      rmax = fmaxf(rmax, __shfl_xor_sync(0xffffffffu, rmax, 4));
      rmax = fmaxf(rmax, __shfl_xor_sync(0xffffffffu, rmax, 8));
      const float mnew = fmaxf(m[r], rmax);
      const float alpha = __expf(m[r] - mnew);
      float rsum = 0.f;
#pragma unroll
      for (int c = 0; c < 4; c++) {
        const float p = __expf(s[r][c] - mnew);
        s[r][c] = p;
        rsum += p;
      }
      rsum += __shfl_xor_sync(0xffffffffu, rsum, 1);
      rsum += __shfl_xor_sync(0xffffffffu, rsum, 2);
      rsum += __shfl_xor_sync(0xffffffffu, rsum, 4);
      rsum += __shfl_xor_sync(0xffffffffu, rsum, 8);
      l[r] = l[r] * alpha + rsum;
      m[r] = mnew;
#pragma unroll
      for (int c = 0; c < 4; c++) o[r][c] *= alpha;
      *(float4*)(Ps + (ty * 4 + r) * 68 + tx * 4) =
          make_float4(s[r][0], s[r][1], s[r][2], s[r][3]);
    }
    __syncthreads();

#pragma unroll 16
    for (int j = 0; j < 64; j++) {
      float a0 = Ps[(ty * 4 + 0) * 68 + j];
      float a1 = Ps[(ty * 4 + 1) * 68 + j];
      float a2 = Ps[(ty * 4 + 2) * 68 + j];
      float a3 = Ps[(ty * 4 + 3) * 68 + j];
      float4 bv = *(const float4*)(Vs + j * 64 + tx * 4);
      o[0][0] += a0 * bv.x; o[0][1] += a0 * bv.y; o[0][2] += a0 * bv.z; o[0][3] += a0 * bv.w;
      o[1][0] += a1 * bv.x; o[1][1] += a1 * bv.y; o[1][2] += a1 * bv.z; o[1][3] += a1 * bv.w;
      o[2][0] += a2 * bv.x; o[2][1] += a2 * bv.y; o[2][2] += a2 * bv.z; o[2][3] += a2 * bv.w;
      o[3][0] += a3 * bv.x; o[3][1] += a3 * bv.y; o[3][2] += a3 * bv.z; o[3][3] += a3 * bv.w;
    }
  }

  float* Og = g_att + ((size_t)bh * TT + qb) * HD;
#pragma unroll
  for (int r = 0; r < 4; r++) {
    const float inv = 1.0f / l[r];
    *(float4*)(Og + (size_t)(ty * 4 + r) * HD + tx * 4) =
        make_float4(o[r][0] * inv, o[r][1] * inv, o[r][2] * inv, o[r][3] * inv);
  }
}

// ---------------------------------------------------------------------------
// Kernel 4: output rotation + unpermute (PROVEN round 4, unchanged).
// ---------------------------------------------------------------------------
__global__ __launch_bounds__(256) void rotary_o_kernel(
    const float* __restrict__ mo) {
  __shared__ float smo[64][65];
  const int bh = blockIdx.y;
  const int b = bh >> 3, nh = bh & 7;
  const int tb = blockIdx.x * 64;
  const int tid = threadIdx.x;
  const float4* src = (const float4*)(g_att + ((size_t)bh * TT + tb) * HD);
#pragma unroll
  for (int i = 0; i < 4; i++) {
    const int pos = tid + i * 256;
    const int trow = pos >> 4;
    const int c4 = pos & 15;
    float4 v = src[pos];
    const int t = tb + trow;
    const float4* mm = (const float4*)(mo + (size_t)t * 128) + c4 * 2;
    float4 m0 = mm[0], m1 = mm[1];
    smo[trow][c4 * 4 + 0] = m0.x * v.x + m0.y * v.y;
    smo[trow][c4 * 4 + 1] = m0.z * v.x + m0.w * v.y;
    smo[trow][c4 * 4 + 2] = m1.x * v.z + m1.y * v.w;
    smo[trow][c4 * 4 + 3] = m1.z * v.z + m1.w * v.w;
  }
  __syncthreads();
  const int d = tid >> 2;
  const int tseg = tid & 3;
  float* dst = g_orot + ((size_t)b * CC + d * 8 + nh) * TT + tb + tseg * 16;
#pragma unroll
  for (int i = 0; i < 4; i++) {
    const int t0 = tseg * 16 + i * 4;
    *(float4*)(dst + i * 4) = make_float4(smo[t0 + 0][d], smo[t0 + 1][d],
                                          smo[t0 + 2][d], smo[t0 + 3][d]);
  }
}

// ---------------------------------------------------------------------------
// Launch: x, w_qkv, b_qkv, w_o, b_o, mat_q, mat_k, mat_v, mat_o
// ---------------------------------------------------------------------------
extern "C" void kernel_launch(void* const* d_in, const int* in_sizes, int n_in,
                              void* d_out, int out_size) {
  const float* x     = (const float*)d_in[0];
  const float* w_qkv = (const float*)d_in[1];
  const float* b_qkv = (const float*)d_in[2];
  const float* w_o   = (const float*)d_in[3];
  const float* b_o   = (const float*)d_in[4];
  const float* mat_q = (const float*)d_in[5];
  const float* mat_k = (const float*)d_in[6];
  const float* mat_v = (const float*)d_in[7];
  const float* mat_o = (const float*)d_in[8];
  float* out = (float*)d_out;

  // QKV projection (tf32), permuted epilogue. B = x (real device pointer).
  mm_tf32_kernel<<<dim3(TT / 128, (3 * CC) / 128, BB), 256>>>(
      w_qkv, x, b_qkv, nullptr, 1, 0);

  // Rotary on q, k, v (in place) — proven
  rotary_qkv_kernel<<<dim3((BB * NH * TT) / 128, 3), 128>>>(mat_q, mat_k,
                                                            mat_v);

  // Attention — PROVEN round-4 fp32 version
  const int ATTN_SMEM =
      (64 * 64 + 64 * 65 + 64 * 64 + 64 * 68) * (int)sizeof(float);
  cudaFuncSetAttribute(attn_kernel, cudaFuncAttributeMaxDynamicSharedMemorySize,
                       ATTN_SMEM);
  attn_kernel<<<dim3(TT / 64, BB * NH), 256, ATTN_SMEM>>>();

  // Output rotary + unpermute to channel-major — proven
  rotary_o_kernel<<<dim3(TT / 64, BB * NH), 256>>>(mat_o);

  // Output projection (tf32) into d_out. B source = g_orot resolved in
  // DEVICE code (the round-5..9 bug: host-side g_orot = host shadow addr).
  mm_tf32_kernel<<<dim3(TT / 128, CC / 128, BB), 256>>>(w_o, nullptr, b_o, out,
                                                        0, 1);
}